// round 2
// baseline (speedup 1.0000x reference)
#include <cuda_runtime.h>
#include <cstdint>

#define HW 50176           // 224*224
#define S_BANDS 371
#define OUT_ELEMS (3*HW)   // 150528

// 2*pi*H*C*1e9 * STRESS_MAGNITUDE  (phase = coef * norm_stress / lambda_nm)
#define PHASE_SCALE 15833.626974092555f

#define MIN_INIT 0x7F7FFFFFu   // FLT_MAX bits (inputs are positive)

static __device__ unsigned g_min_bits    = MIN_INIT;
static __device__ unsigned g_max_bits    = 0u;
static __device__ unsigned g_isomax_bits = 0u;
static __device__ unsigned g_ticket      = 0u;
static __device__ float    g_wsum[3];

// ---------------------------------------------------------------------------
// Kernel 1: chip-wide min/max. 49 blocks x 256 threads, one float4 each.
// Positive floats: uint bit ordering == float ordering -> atomicMin/Max on bits.
// Block 0 warp 1 also computes the per-channel weight sums.
// ---------------------------------------------------------------------------
__global__ void __launch_bounds__(256) minmax_kernel(const float* __restrict__ sm,
                                                     const float* __restrict__ ss) {
    const int tid = threadIdx.x;
    const int i = blockIdx.x * 256 + tid;          // 0 .. 12543

    float4 v = ((const float4*)sm)[i];
    float mn = fminf(fminf(v.x, v.y), fminf(v.z, v.w));
    float mx = fmaxf(fmaxf(v.x, v.y), fmaxf(v.z, v.w));
    #pragma unroll
    for (int o = 16; o; o >>= 1) {
        mn = fminf(mn, __shfl_xor_sync(0xFFFFFFFFu, mn, o));
        mx = fmaxf(mx, __shfl_xor_sync(0xFFFFFFFFu, mx, o));
    }
    if ((tid & 31) == 0) {
        atomicMin(&g_min_bits, __float_as_uint(mn));
        atomicMax(&g_max_bits, __float_as_uint(mx));
    }

    if (blockIdx.x == 0 && tid >= 32 && tid < 64) {
        int l = tid - 32;
        float w0 = 0.f, w1 = 0.f, w2 = 0.f;
        for (int s = l; s < S_BANDS; s += 32) {
            w0 += ss[3 * s + 0];
            w1 += ss[3 * s + 1];
            w2 += ss[3 * s + 2];
        }
        #pragma unroll
        for (int o = 16; o; o >>= 1) {
            w0 += __shfl_xor_sync(0xFFFFFFFFu, w0, o);
            w1 += __shfl_xor_sync(0xFFFFFFFFu, w1, o);
            w2 += __shfl_xor_sync(0xFFFFFFFFu, w2, o);
        }
        if (l == 0) {
            g_wsum[0] = 0.5f * w0;
            g_wsum[1] = 0.5f * w1;
            g_wsum[2] = 0.5f * w2;
        }
    }
}

// ---------------------------------------------------------------------------
// Kernel 2: main compute. One thread per pixel; 371-band loop (MUFU-bound).
// iso_c = Wsum_c - sum_s w_sc * cos(t * q_s).  Unnormalized iso -> out
// (channel-major), global max tracked via atomicMax on bits.
// ---------------------------------------------------------------------------
__global__ void __launch_bounds__(256) fringe_kernel(const float* __restrict__ sm,
                                                     const float* __restrict__ ss,
                                                     float* __restrict__ out) {
    __shared__ float4 tab[S_BANDS];   // {1/lambda, w0, w1, w2}
    const int tid = threadIdx.x;

    for (int s = tid; s < S_BANDS; s += 256) {
        float lam = 390.0f + (float)s;
        tab[s] = make_float4(1.0f / lam,
                             0.5f * ss[3 * s + 0],
                             0.5f * ss[3 * s + 1],
                             0.5f * ss[3 * s + 2]);
    }
    __syncthreads();

    const float mn    = __uint_as_float(g_min_bits);
    const float mx    = __uint_as_float(g_max_bits);
    const float scale = PHASE_SCALE / (mx - mn);

    const int p = blockIdx.x * 256 + tid;
    const float t = (sm[p] - mn) * scale;

    float a0 = 0.f, a1 = 0.f, a2 = 0.f;
    #pragma unroll 7
    for (int s = 0; s < S_BANDS; s++) {
        float4 v = tab[s];
        float c = __cosf(t * v.x);          // single MUFU.COS
        a0 = fmaf(v.y, c, a0);
        a1 = fmaf(v.z, c, a1);
        a2 = fmaf(v.w, c, a2);
    }

    const float i0 = g_wsum[0] - a0;
    const float i1 = g_wsum[1] - a1;
    const float i2 = g_wsum[2] - a2;

    out[p]          = i0;
    out[HW + p]     = i1;
    out[2 * HW + p] = i2;

    float m = fmaxf(i0, fmaxf(i1, i2));
    #pragma unroll
    for (int o = 16; o; o >>= 1) m = fmaxf(m, __shfl_xor_sync(0xFFFFFFFFu, m, o));
    if ((tid & 31) == 0) atomicMax(&g_isomax_bits, __float_as_uint(m));
}

// ---------------------------------------------------------------------------
// Kernel 3: normalize in place (float4). The last block to finish (atomic
// ticket, after __syncthreads so every thread of it has already read the max)
// re-arms the global atomics for the next graph replay.
// ---------------------------------------------------------------------------
__global__ void __launch_bounds__(256) norm_kernel(float* __restrict__ out) {
    const int i = blockIdx.x * 256 + threadIdx.x;
    const float inv = 1.0f / __uint_as_float(g_isomax_bits);
    if (i < OUT_ELEMS / 4) {
        float4 v = ((float4*)out)[i];
        v.x *= inv; v.y *= inv; v.z *= inv; v.w *= inv;
        ((float4*)out)[i] = v;
    }
    __syncthreads();
    if (threadIdx.x == 0) {
        __threadfence();
        unsigned t = atomicAdd(&g_ticket, 1u);
        if (t == gridDim.x - 1) {               // last block: restore invariant
            g_min_bits    = MIN_INIT;
            g_max_bits    = 0u;
            g_isomax_bits = 0u;
            g_ticket      = 0u;
            __threadfence();
        }
    }
}

extern "C" void kernel_launch(void* const* d_in, const int* in_sizes, int n_in,
                              void* d_out, int out_size) {
    const float* sm = (const float*)d_in[0];
    const float* ss = (const float*)d_in[1];
    if (in_sizes[0] != HW) {  // defensive: identify by element count
        sm = (const float*)d_in[1];
        ss = (const float*)d_in[0];
    }
    float* out = (float*)d_out;

    minmax_kernel<<<HW / 4 / 256, 256>>>(sm, ss);            // 49 blocks
    fringe_kernel<<<HW / 256, 256>>>(sm, ss, out);           // 196 blocks
    norm_kernel<<<(OUT_ELEMS / 4 + 255) / 256, 256>>>(out);  // 147 blocks
}

// round 5
// speedup vs baseline: 1.2899x; 1.2899x over previous
#include <cuda_runtime.h>
#include <cstdint>

#define HW 50176            // 224*224
#define S_BANDS 371
#define LUT_N 8192

// 2*pi*H*C*1e9 * STRESS_MAGNITUDE
#define PHASE_SCALE 15833.626974092555f
#define MIN_INIT 0x7F7FFFFFu   // FLT_MAX bits (inputs are in [0,1])

static __device__ unsigned g_min_bits    = MIN_INIT;
static __device__ unsigned g_max_bits    = 0u;
static __device__ unsigned g_lutmax_bits = 0u;
static __device__ unsigned g_ticket      = 0u;
static __device__ float4   g_lut[LUT_N];       // {F0, F1, F2, unused}

// ---------------------------------------------------------------------------
// K1: chip-wide min/max of the stressmap. 49 blocks x 256 thr, 1 float4 each.
// Positive floats: uint ordering == float ordering.
// ---------------------------------------------------------------------------
__global__ void __launch_bounds__(256) minmax_kernel(const float* __restrict__ sm) {
    const int tid = threadIdx.x;
    const int i = blockIdx.x * 256 + tid;          // 0 .. 12543
    float4 v = ((const float4*)sm)[i];
    float mn = fminf(fminf(v.x, v.y), fminf(v.z, v.w));
    float mx = fmaxf(fmaxf(v.x, v.y), fmaxf(v.z, v.w));
    #pragma unroll
    for (int o = 16; o; o >>= 1) {
        mn = fminf(mn, __shfl_xor_sync(0xFFFFFFFFu, mn, o));
        mx = fmaxf(mx, __shfl_xor_sync(0xFFFFFFFFu, mx, o));
    }
    if ((tid & 31) == 0) {
        atomicMin(&g_min_bits, __float_as_uint(mn));
        atomicMax(&g_max_bits, __float_as_uint(mx));
    }
}

// ---------------------------------------------------------------------------
// K2: build the LUT.  F_c(f_i) = sum_s 0.5*w_sc*(1 - cos(f_i*PHASE_SCALE/lam_s))
// One entry per thread; 128 blocks x 64 threads. Also atomicMax the LUT max.
// Independent of K1 (f is the normalized fraction, data-independent).
// ---------------------------------------------------------------------------
__global__ void __launch_bounds__(64) lut_kernel(const float* __restrict__ ss) {
    __shared__ float4 tab[S_BANDS];   // {1/lambda, w0, w1, w2}
    const int tid = threadIdx.x;

    for (int s = tid; s < S_BANDS; s += 64) {
        tab[s] = make_float4(1.0f / (390.0f + (float)s),
                             ss[3 * s + 0], ss[3 * s + 1], ss[3 * s + 2]);
    }
    __syncthreads();

    const int i = blockIdx.x * 64 + tid;           // 0 .. 8191
    const float t = (float)i * (PHASE_SCALE / (float)(LUT_N - 1));

    float a0 = 0.f, a1 = 0.f, a2 = 0.f;            // sum w*cos
    float w0 = 0.f, w1 = 0.f, w2 = 0.f;            // sum w
    #pragma unroll 7
    for (int s = 0; s < S_BANDS; s++) {
        float4 v = tab[s];
        float c = __cosf(t * v.x);
        a0 = fmaf(v.y, c, a0);  w0 += v.y;
        a1 = fmaf(v.z, c, a1);  w1 += v.z;
        a2 = fmaf(v.w, c, a2);  w2 += v.w;
    }
    const float F0 = 0.5f * (w0 - a0);
    const float F1 = 0.5f * (w1 - a1);
    const float F2 = 0.5f * (w2 - a2);
    g_lut[i] = make_float4(F0, F1, F2, 0.f);

    float m = fmaxf(F0, fmaxf(F1, F2));
    #pragma unroll
    for (int o = 16; o; o >>= 1) m = fmaxf(m, __shfl_xor_sync(0xFFFFFFFFu, m, o));
    if ((tid & 31) == 0) atomicMax(&g_lutmax_bits, __float_as_uint(m));
}

// ---------------------------------------------------------------------------
// K3: per-pixel lerp + normalize + store. 196 blocks x 256 thr, 1 pixel each.
// Last-ticket block re-arms the globals (no waiting -> no hang hazard).
// ---------------------------------------------------------------------------
__global__ void __launch_bounds__(256) pixel_kernel(const float* __restrict__ sm,
                                                    float* __restrict__ out) {
    __shared__ float s_mn, s_invrng, s_inv;
    const int tid = threadIdx.x;

    if (tid == 0) {
        const float mn = __uint_as_float(g_min_bits);
        const float mx = __uint_as_float(g_max_bits);
        s_mn     = mn;
        s_invrng = (float)(LUT_N - 1) / (mx - mn);
        s_inv    = 1.0f / __uint_as_float(g_lutmax_bits);
    }
    __syncthreads();

    const int p = blockIdx.x * 256 + tid;
    const float u  = (sm[p] - s_mn) * s_invrng;            // 0 .. LUT_N-1
    int   i    = (int)u;
    i = (i < 0) ? 0 : ((i > LUT_N - 2) ? LUT_N - 2 : i);
    const float fr = u - (float)i;

    const float4 a = g_lut[i];
    const float4 b = g_lut[i + 1];
    const float inv = s_inv;
    out[p]          = fmaf(fr, b.x - a.x, a.x) * inv;
    out[HW + p]     = fmaf(fr, b.y - a.y, a.y) * inv;
    out[2 * HW + p] = fmaf(fr, b.z - a.z, a.z) * inv;

    // ---- last-one-out reset (no spinning). This block's global reads all
    // happened before its ticket; reset runs only after every block ticked.
    if (tid == 0) {
        __threadfence();
        unsigned t = atomicAdd(&g_ticket, 1u);
        if (t == gridDim.x - 1) {
            g_min_bits    = MIN_INIT;
            g_max_bits    = 0u;
            g_lutmax_bits = 0u;
            g_ticket      = 0u;
            __threadfence();
        }
    }
}

extern "C" void kernel_launch(void* const* d_in, const int* in_sizes, int n_in,
                              void* d_out, int out_size) {
    const float* sm = (const float*)d_in[0];
    const float* ss = (const float*)d_in[1];
    if (in_sizes[0] != HW) {   // defensive: identify by element count
        sm = (const float*)d_in[1];
        ss = (const float*)d_in[0];
    }
    float* out = (float*)d_out;

    minmax_kernel<<<HW / 4 / 256, 256>>>(sm);        // 49 blocks
    lut_kernel<<<LUT_N / 64, 64>>>(ss);              // 128 blocks
    pixel_kernel<<<HW / 256, 256>>>(sm, out);        // 196 blocks
}

// round 6
// speedup vs baseline: 1.2949x; 1.0039x over previous
#include <cuda_runtime.h>
#include <cstdint>

#define HW 50176            // 224*224
#define S_BANDS 371
#define LUT_N 8192

// 2*pi*H*C*1e9 * STRESS_MAGNITUDE
#define PHASE_SCALE 15833.626974092555f
#define MIN_INIT 0x7F7FFFFFu   // FLT_MAX bits (inputs are in [0,1])

#define MM_BLOCKS 49                   // minmax: 49*256 threads, 1 float4 each
#define LUT_BLOCKS (LUT_N / 256)       // 32
#define K12_BLOCKS (MM_BLOCKS + LUT_BLOCKS)   // 81

static __device__ unsigned g_min_bits    = MIN_INIT;
static __device__ unsigned g_max_bits    = 0u;
static __device__ unsigned g_lutmax_bits = 0u;
static __device__ unsigned g_ticket      = 0u;
static __device__ float4   g_lut[LUT_N];       // {F0, F1, F2, pad}

// ---------------------------------------------------------------------------
// K12: fused min/max + LUT build (independent phases on disjoint block ranges).
//   blocks [0,49):  chip-wide min/max of stressmap (atomicMin/Max on bits)
//   blocks [49,81): LUT entries F_c(f_i) = sum_s 0.5*w_sc*(1-cos(f_i*PS/lam_s))
//                   + atomicMax of the LUT max
// ---------------------------------------------------------------------------
__global__ void __launch_bounds__(256) k12_kernel(const float* __restrict__ sm,
                                                  const float* __restrict__ ss) {
    const int tid = threadIdx.x;

    if (blockIdx.x < MM_BLOCKS) {
        // ---- min/max part ----
        const int i = blockIdx.x * 256 + tid;          // 0 .. 12543
        float4 v = ((const float4*)sm)[i];
        float mn = fminf(fminf(v.x, v.y), fminf(v.z, v.w));
        float mx = fmaxf(fmaxf(v.x, v.y), fmaxf(v.z, v.w));
        #pragma unroll
        for (int o = 16; o; o >>= 1) {
            mn = fminf(mn, __shfl_xor_sync(0xFFFFFFFFu, mn, o));
            mx = fmaxf(mx, __shfl_xor_sync(0xFFFFFFFFu, mx, o));
        }
        if ((tid & 31) == 0) {
            atomicMin(&g_min_bits, __float_as_uint(mn));
            atomicMax(&g_max_bits, __float_as_uint(mx));
        }
    } else {
        // ---- LUT part ----
        __shared__ float4 tab[S_BANDS];   // {1/lambda, w0, w1, w2}
        for (int s = tid; s < S_BANDS; s += 256) {
            tab[s] = make_float4(1.0f / (390.0f + (float)s),
                                 ss[3 * s + 0], ss[3 * s + 1], ss[3 * s + 2]);
        }
        __syncthreads();

        const int i = (blockIdx.x - MM_BLOCKS) * 256 + tid;   // 0 .. 8191
        const float t = (float)i * (PHASE_SCALE / (float)(LUT_N - 1));

        float a0 = 0.f, a1 = 0.f, a2 = 0.f;            // sum w*cos
        float w0 = 0.f, w1 = 0.f, w2 = 0.f;            // sum w
        #pragma unroll 7
        for (int s = 0; s < S_BANDS; s++) {
            float4 v = tab[s];
            float c = __cosf(t * v.x);
            a0 = fmaf(v.y, c, a0);  w0 += v.y;
            a1 = fmaf(v.z, c, a1);  w1 += v.z;
            a2 = fmaf(v.w, c, a2);  w2 += v.w;
        }
        const float F0 = 0.5f * (w0 - a0);
        const float F1 = 0.5f * (w1 - a1);
        const float F2 = 0.5f * (w2 - a2);
        g_lut[i] = make_float4(F0, F1, F2, 0.f);

        float m = fmaxf(F0, fmaxf(F1, F2));
        #pragma unroll
        for (int o = 16; o; o >>= 1) m = fmaxf(m, __shfl_xor_sync(0xFFFFFFFFu, m, o));
        if ((tid & 31) == 0) atomicMax(&g_lutmax_bits, __float_as_uint(m));
    }
}

// ---------------------------------------------------------------------------
// K3: per-pixel lerp + normalize + store, x4 vectorized.
// 49 blocks x 256 thr; each thread: 1 LDG.128 of sm, 8 LUT gathers,
// 3 STG.128 (one per channel plane). Last-ticket block re-arms globals.
// ---------------------------------------------------------------------------
__global__ void __launch_bounds__(256) pixel_kernel(const float* __restrict__ sm,
                                                    float* __restrict__ out) {
    __shared__ float s_mn, s_invrng, s_inv;
    const int tid = threadIdx.x;

    if (tid == 0) {
        const float mn = __uint_as_float(g_min_bits);
        const float mx = __uint_as_float(g_max_bits);
        s_mn     = mn;
        s_invrng = (float)(LUT_N - 1) / (mx - mn);
        s_inv    = 1.0f / __uint_as_float(g_lutmax_bits);
    }
    __syncthreads();

    const int p4 = blockIdx.x * 256 + tid;          // 0 .. 12543
    const float4 x = ((const float4*)sm)[p4];
    const float mn = s_mn, invrng = s_invrng, inv = s_inv;

    float r0[4], r1[4], r2[4];
    const float xs[4] = {x.x, x.y, x.z, x.w};
    #pragma unroll
    for (int k = 0; k < 4; k++) {
        float u = (xs[k] - mn) * invrng;            // 0 .. LUT_N-1
        int   i = (int)u;
        i = (i < 0) ? 0 : ((i > LUT_N - 2) ? LUT_N - 2 : i);
        float fr = u - (float)i;
        float4 a = g_lut[i];
        float4 b = g_lut[i + 1];
        r0[k] = fmaf(fr, b.x - a.x, a.x) * inv;
        r1[k] = fmaf(fr, b.y - a.y, a.y) * inv;
        r2[k] = fmaf(fr, b.z - a.z, a.z) * inv;
    }

    float4* o4 = (float4*)out;
    o4[p4]               = make_float4(r0[0], r0[1], r0[2], r0[3]);
    o4[HW / 4 + p4]      = make_float4(r1[0], r1[1], r1[2], r1[3]);
    o4[2 * HW / 4 + p4]  = make_float4(r2[0], r2[1], r2[2], r2[3]);

    // ---- last-one-out reset (no spinning). This block's global reads all
    // happened before its ticket; reset runs only after every block ticked.
    if (tid == 0) {
        __threadfence();
        unsigned t = atomicAdd(&g_ticket, 1u);
        if (t == gridDim.x - 1) {
            g_min_bits    = MIN_INIT;
            g_max_bits    = 0u;
            g_lutmax_bits = 0u;
            g_ticket      = 0u;
            __threadfence();
        }
    }
}

extern "C" void kernel_launch(void* const* d_in, const int* in_sizes, int n_in,
                              void* d_out, int out_size) {
    const float* sm = (const float*)d_in[0];
    const float* ss = (const float*)d_in[1];
    if (in_sizes[0] != HW) {   // defensive: identify by element count
        sm = (const float*)d_in[1];
        ss = (const float*)d_in[0];
    }
    float* out = (float*)d_out;

    k12_kernel<<<K12_BLOCKS, 256>>>(sm, ss);         // 81 blocks
    pixel_kernel<<<HW / 4 / 256, 256>>>(sm, out);    // 49 blocks
}

// round 7
// speedup vs baseline: 1.7221x; 1.3299x over previous
#include <cuda_runtime.h>
#include <cstdint>

#define HW 50176            // 224*224
#define S_BANDS 371
#define LUT_N 4096

// 2*pi*H*C*1e9 * STRESS_MAGNITUDE
#define PHASE_SCALE 15833.626974092555f
#define MIN_INIT 0x7F7FFFFFu   // FLT_MAX bits (inputs are in [0,1])

#define MM_BLOCKS 49                    // minmax: 49*256 threads, 1 float4 each
#define ENT_PER_BLK 64                  // LUT entries per block (4 thr/entry)
#define LUT_BLOCKS (LUT_N / ENT_PER_BLK)        // 64
#define K12_BLOCKS (MM_BLOCKS + LUT_BLOCKS)     // 113 <= 148 -> one wave

static __device__ unsigned g_min_bits    = MIN_INIT;
static __device__ unsigned g_max_bits    = 0u;
static __device__ unsigned g_lutmax_bits = 0u;
static __device__ unsigned g_ticket      = 0u;
static __device__ float4   g_lut[LUT_N];       // {F0, F1, F2, pad}

// ---------------------------------------------------------------------------
// K12: fused min/max + LUT build on disjoint block ranges.
//   blocks [0,49):   chip-wide min/max of stressmap (atomics on bits)
//   blocks [49,113): LUT. 4 threads cooperate per entry (93-band MUFU chains
//                    instead of 371) -> ~4x shorter critical path.
// ---------------------------------------------------------------------------
__global__ void __launch_bounds__(256) k12_kernel(const float* __restrict__ sm,
                                                  const float* __restrict__ ss) {
    const int tid = threadIdx.x;

    if (blockIdx.x < MM_BLOCKS) {
        const int i = blockIdx.x * 256 + tid;          // 0 .. 12543
        float4 v = ((const float4*)sm)[i];
        float mn = fminf(fminf(v.x, v.y), fminf(v.z, v.w));
        float mx = fmaxf(fmaxf(v.x, v.y), fmaxf(v.z, v.w));
        #pragma unroll
        for (int o = 16; o; o >>= 1) {
            mn = fminf(mn, __shfl_xor_sync(0xFFFFFFFFu, mn, o));
            mx = fmaxf(mx, __shfl_xor_sync(0xFFFFFFFFu, mx, o));
        }
        if ((tid & 31) == 0) {
            atomicMin(&g_min_bits, __float_as_uint(mn));
            atomicMax(&g_max_bits, __float_as_uint(mx));
        }
    } else {
        __shared__ float4 tab[S_BANDS];        // {1/lambda, w0, w1, w2}
        __shared__ float  s_a[3][256];         // per-thread partials (w - wcos)

        for (int s = tid; s < S_BANDS; s += 256) {
            tab[s] = make_float4(1.0f / (390.0f + (float)s),
                                 ss[3 * s + 0], ss[3 * s + 1], ss[3 * s + 2]);
        }
        __syncthreads();

        const int e = tid & (ENT_PER_BLK - 1);          // entry within block
        const int q = tid >> 6;                         // band quarter 0..3
        const int i = (blockIdx.x - MM_BLOCKS) * ENT_PER_BLK + e;   // LUT index
        const float t = (float)i * (PHASE_SCALE / (float)(LUT_N - 1));

        const int s0 = q * 93;
        const int s1 = (q == 3) ? S_BANDS : s0 + 93;

        // partial of sum_s w_sc*(1 - cos(t/lam_s)) over this quarter
        float a0 = 0.f, a1 = 0.f, a2 = 0.f;
        for (int s = s0; s < s1; s++) {
            float4 v = tab[s];
            float c = 1.0f - __cosf(t * v.x);
            a0 = fmaf(v.y, c, a0);
            a1 = fmaf(v.z, c, a1);
            a2 = fmaf(v.w, c, a2);
        }
        s_a[0][tid] = a0; s_a[1][tid] = a1; s_a[2][tid] = a2;
        __syncthreads();

        if (q == 0) {
            const float F0 = 0.5f * (s_a[0][e] + s_a[0][e + 64] + s_a[0][e + 128] + s_a[0][e + 192]);
            const float F1 = 0.5f * (s_a[1][e] + s_a[1][e + 64] + s_a[1][e + 128] + s_a[1][e + 192]);
            const float F2 = 0.5f * (s_a[2][e] + s_a[2][e + 64] + s_a[2][e + 128] + s_a[2][e + 192]);
            g_lut[i] = make_float4(F0, F1, F2, 0.f);

            float m = fmaxf(F0, fmaxf(F1, F2));
            #pragma unroll
            for (int o = 16; o; o >>= 1) m = fmaxf(m, __shfl_xor_sync(0xFFFFFFFFu, m, o));
            if ((tid & 31) == 0) atomicMax(&g_lutmax_bits, __float_as_uint(m));
        }
    }
}

// ---------------------------------------------------------------------------
// K3: per-pixel lerp + normalize + store, x4 vectorized, PDL-launched.
// Loads its input BEFORE cudaGridDependencySynchronize() so the load overlaps
// K12's tail. Last-ticket block re-arms globals (no spinning).
// ---------------------------------------------------------------------------
__global__ void __launch_bounds__(256) pixel_kernel(const float* __restrict__ sm,
                                                    float* __restrict__ out) {
    __shared__ float s_mn, s_invrng, s_inv;
    const int tid = threadIdx.x;
    const int p4  = blockIdx.x * 256 + tid;          // 0 .. 12543

    const float4 x = ((const float4*)sm)[p4];        // independent of K12

    cudaGridDependencySynchronize();                 // K12's writes now visible

    if (tid == 0) {
        const float mn = __uint_as_float(g_min_bits);
        const float mx = __uint_as_float(g_max_bits);
        s_mn     = mn;
        s_invrng = (float)(LUT_N - 1) / (mx - mn);
        s_inv    = 1.0f / __uint_as_float(g_lutmax_bits);
    }
    __syncthreads();

    const float mn = s_mn, invrng = s_invrng, inv = s_inv;
    float r0[4], r1[4], r2[4];
    const float xs[4] = {x.x, x.y, x.z, x.w};
    #pragma unroll
    for (int k = 0; k < 4; k++) {
        float u = (xs[k] - mn) * invrng;             // 0 .. LUT_N-1
        int   i = (int)u;
        i = (i < 0) ? 0 : ((i > LUT_N - 2) ? LUT_N - 2 : i);
        float fr = u - (float)i;
        float4 a = g_lut[i];
        float4 b = g_lut[i + 1];
        r0[k] = fmaf(fr, b.x - a.x, a.x) * inv;
        r1[k] = fmaf(fr, b.y - a.y, a.y) * inv;
        r2[k] = fmaf(fr, b.z - a.z, a.z) * inv;
    }

    float4* o4 = (float4*)out;
    o4[p4]              = make_float4(r0[0], r0[1], r0[2], r0[3]);
    o4[HW / 4 + p4]     = make_float4(r1[0], r1[1], r1[2], r1[3]);
    o4[2 * HW / 4 + p4] = make_float4(r2[0], r2[1], r2[2], r2[3]);

    // last-one-out reset: every block's global reads precede its ticket.
    if (tid == 0) {
        __threadfence();
        unsigned t = atomicAdd(&g_ticket, 1u);
        if (t == gridDim.x - 1) {
            g_min_bits    = MIN_INIT;
            g_max_bits    = 0u;
            g_lutmax_bits = 0u;
            g_ticket      = 0u;
            __threadfence();
        }
    }
}

extern "C" void kernel_launch(void* const* d_in, const int* in_sizes, int n_in,
                              void* d_out, int out_size) {
    const float* sm = (const float*)d_in[0];
    const float* ss = (const float*)d_in[1];
    if (in_sizes[0] != HW) {   // defensive: identify by element count
        sm = (const float*)d_in[1];
        ss = (const float*)d_in[0];
    }
    float* out = (float*)d_out;

    k12_kernel<<<K12_BLOCKS, 256>>>(sm, ss);         // 113 blocks, one wave

    // PDL: pixel kernel launches early; it self-orders via griddepsync.
    cudaLaunchConfig_t cfg = {};
    cfg.gridDim  = dim3(HW / 4 / 256);               // 49 blocks
    cfg.blockDim = dim3(256);
    cudaLaunchAttribute attr[1];
    attr[0].id = cudaLaunchAttributeProgrammaticStreamSerialization;
    attr[0].val.programmaticStreamSerializationAllowed = 1;
    cfg.attrs = attr;
    cfg.numAttrs = 1;
    cudaLaunchKernelEx(&cfg, pixel_kernel, sm, out);
}

// round 9
// speedup vs baseline: 2.0654x; 1.1994x over previous
#include <cuda_runtime.h>
#include <cstdint>

#define HW 50176            // 224*224
#define S_BANDS 371
#define LUT_N 2048

// 2*pi*H*C*1e9 * STRESS_MAGNITUDE
#define PHASE_SCALE 15833.626974092555f
#define MIN_INIT 0x7F7FFFFFu   // FLT_MAX bits (inputs are in [0,1])

#define MM_BLOCKS 49                     // minmax: 49*256 threads, 1 float4 each
#define ENT_PER_BLK 32                   // LUT entries per block (8 thr/entry)
#define LUT_BLOCKS (LUT_N / ENT_PER_BLK)         // 64
#define K12_BLOCKS (MM_BLOCKS + LUT_BLOCKS)      // 113 <= 148 -> one wave

// stats packed in one 16B struct: one LDG.128 fetches all three + ticket slot
// .x = min bits, .y = max bits, .z = lutmax bits, .w = ticket
static __device__ uint4  g_stats = {MIN_INIT, 0u, 0u, 0u};
static __device__ float4 g_lut[LUT_N];          // {F0, F1, F2, pad}

// ---------------------------------------------------------------------------
// K12: fused min/max + LUT build on disjoint block ranges.
//   blocks [0,49):   chip-wide min/max of stressmap (atomics on g_stats.x/.y)
//   blocks [49,113): LUT. 8 threads cooperate per entry (<=47-band MUFU chain).
// ---------------------------------------------------------------------------
__global__ void __launch_bounds__(256) k12_kernel(const float* __restrict__ sm,
                                                  const float* __restrict__ ss) {
    const int tid = threadIdx.x;

    if (blockIdx.x < MM_BLOCKS) {
        const int i = blockIdx.x * 256 + tid;          // 0 .. 12543
        float4 v = ((const float4*)sm)[i];
        float mn = fminf(fminf(v.x, v.y), fminf(v.z, v.w));
        float mx = fmaxf(fmaxf(v.x, v.y), fmaxf(v.z, v.w));
        #pragma unroll
        for (int o = 16; o; o >>= 1) {
            mn = fminf(mn, __shfl_xor_sync(0xFFFFFFFFu, mn, o));
            mx = fmaxf(mx, __shfl_xor_sync(0xFFFFFFFFu, mx, o));
        }
        if ((tid & 31) == 0) {
            atomicMin(&g_stats.x, __float_as_uint(mn));
            atomicMax(&g_stats.y, __float_as_uint(mx));
        }
    } else {
        __shared__ float4 tab[S_BANDS];        // {1/lambda, w0, w1, w2}
        __shared__ float  s_a[3][256];         // per-thread partials

        for (int s = tid; s < S_BANDS; s += 256) {
            tab[s] = make_float4(1.0f / (390.0f + (float)s),
                                 ss[3 * s + 0], ss[3 * s + 1], ss[3 * s + 2]);
        }
        __syncthreads();

        const int e = tid & (ENT_PER_BLK - 1);          // entry within block
        const int q = tid >> 5;                         // band octant 0..7
        const int i = (blockIdx.x - MM_BLOCKS) * ENT_PER_BLK + e;   // LUT index
        const float t = (float)i * (PHASE_SCALE / (float)(LUT_N - 1));

        const int s0 = q * 47;
        const int s1 = (q == 7) ? S_BANDS : s0 + 47;    // last octant: 42 bands

        // partial of sum_s w_sc*(1 - cos(t/lam_s)) over this octant
        float a0 = 0.f, a1 = 0.f, a2 = 0.f;
        for (int s = s0; s < s1; s++) {
            float4 v = tab[s];
            float c = 1.0f - __cosf(t * v.x);
            a0 = fmaf(v.y, c, a0);
            a1 = fmaf(v.z, c, a1);
            a2 = fmaf(v.w, c, a2);
        }
        s_a[0][tid] = a0; s_a[1][tid] = a1; s_a[2][tid] = a2;
        __syncthreads();

        if (q == 0) {   // warp 0 finalizes the block's 32 entries
            float F[3];
            #pragma unroll
            for (int c = 0; c < 3; c++) {
                float acc = s_a[c][e];
                #pragma unroll
                for (int w = 1; w < 8; w++) acc += s_a[c][e + 32 * w];
                F[c] = 0.5f * acc;
            }
            g_lut[i] = make_float4(F[0], F[1], F[2], 0.f);

            float m = fmaxf(F[0], fmaxf(F[1], F[2]));
            #pragma unroll
            for (int o = 16; o; o >>= 1) m = fmaxf(m, __shfl_xor_sync(0xFFFFFFFFu, m, o));
            if (e == 0) atomicMax(&g_stats.z, __float_as_uint(m));
        }
    }
}

// ---------------------------------------------------------------------------
// K3: per-pixel lerp + normalize + store, x2 (float2), PDL-launched.
// 98 blocks x 256 thr -> one wave across all SMs. Input load issued BEFORE
// cudaGridDependencySynchronize(). Last-ticket block re-arms globals.
// ---------------------------------------------------------------------------
__global__ void __launch_bounds__(256) pixel_kernel(const float* __restrict__ sm,
                                                    float* __restrict__ out) {
    __shared__ float s_mn, s_invrng, s_inv;
    const int tid = threadIdx.x;
    const int p2  = blockIdx.x * 256 + tid;          // 0 .. 25087

    const float2 x = ((const float2*)sm)[p2];        // independent of K12

    cudaGridDependencySynchronize();                 // K12's writes now visible

    if (tid == 0) {
        unsigned sx, sy, sz, sw;
        asm volatile("ld.global.v4.u32 {%0,%1,%2,%3}, [%4];"
                     : "=r"(sx), "=r"(sy), "=r"(sz), "=r"(sw)
                     : "l"(&g_stats) : "memory");    // one LDG.128
        const float mn = __uint_as_float(sx);
        const float mx = __uint_as_float(sy);
        s_mn     = mn;
        s_invrng = (float)(LUT_N - 1) / (mx - mn);
        s_inv    = 1.0f / __uint_as_float(sz);
        (void)sw;
    }
    __syncthreads();

    const float mn = s_mn, invrng = s_invrng, inv = s_inv;
    float r0[2], r1[2], r2[2];
    const float xs[2] = {x.x, x.y};
    #pragma unroll
    for (int k = 0; k < 2; k++) {
        float u = (xs[k] - mn) * invrng;             // 0 .. LUT_N-1
        int   i = (int)u;
        i = (i < 0) ? 0 : ((i > LUT_N - 2) ? LUT_N - 2 : i);
        float fr = u - (float)i;
        float4 a = g_lut[i];
        float4 b = g_lut[i + 1];
        r0[k] = fmaf(fr, b.x - a.x, a.x) * inv;
        r1[k] = fmaf(fr, b.y - a.y, a.y) * inv;
        r2[k] = fmaf(fr, b.z - a.z, a.z) * inv;
    }

    float2* o2 = (float2*)out;
    o2[p2]              = make_float2(r0[0], r0[1]);
    o2[HW / 2 + p2]     = make_float2(r1[0], r1[1]);
    o2[HW + p2]         = make_float2(r2[0], r2[1]);

    // last-one-out reset: every block's global reads precede its ticket.
    if (tid == 0) {
        __threadfence();
        unsigned t = atomicAdd(&g_stats.w, 1u);
        if (t == gridDim.x - 1) {
            g_stats.x = MIN_INIT;
            g_stats.y = 0u;
            g_stats.z = 0u;
            g_stats.w = 0u;
            __threadfence();
        }
    }
}

extern "C" void kernel_launch(void* const* d_in, const int* in_sizes, int n_in,
                              void* d_out, int out_size) {
    const float* sm = (const float*)d_in[0];
    const float* ss = (const float*)d_in[1];
    if (in_sizes[0] != HW) {   // defensive: identify by element count
        sm = (const float*)d_in[1];
        ss = (const float*)d_in[0];
    }
    float* out = (float*)d_out;

    k12_kernel<<<K12_BLOCKS, 256>>>(sm, ss);         // 113 blocks, one wave

    // PDL: pixel kernel launches early; orders itself via griddepsync.
    cudaLaunchConfig_t cfg = {};
    cfg.gridDim  = dim3(HW / 2 / 256);               // 98 blocks, one wave
    cfg.blockDim = dim3(256);
    cudaLaunchAttribute attr[1];
    attr[0].id = cudaLaunchAttributeProgrammaticStreamSerialization;
    attr[0].val.programmaticStreamSerializationAllowed = 1;
    cfg.attrs = attr;
    cfg.numAttrs = 1;
    cudaLaunchKernelEx(&cfg, pixel_kernel, sm, out);
}

// round 10
// speedup vs baseline: 2.0719x; 1.0031x over previous
#include <cuda_runtime.h>
#include <cstdint>

#define HW 50176            // 224*224
#define S_BANDS 371
#define LUT_N 1024

// 2*pi*H*C*1e9 * STRESS_MAGNITUDE
#define PHASE_SCALE 15833.626974092555f
#define MIN_INIT 0x7F7FFFFFu   // FLT_MAX bits (inputs are in [0,1])

#define K12_TPB 128
#define MM_BLOCKS 98                     // 98*128 threads, 1 float4 each = 12544
#define ENT_PER_BLK 16                   // LUT entries per block (8 thr/entry)
#define LUT_BLOCKS (LUT_N / ENT_PER_BLK)         // 64
#define K12_BLOCKS (MM_BLOCKS + LUT_BLOCKS)      // 162 x 128thr -> ~1 blk/SM

// stats packed in one 16B struct: one LDG.128 fetches all three + ticket slot
// .x = min bits, .y = max bits, .z = lutmax bits, .w = ticket
static __device__ uint4  g_stats = {MIN_INIT, 0u, 0u, 0u};
static __device__ float4 g_lut[LUT_N];          // {F0, F1, F2, pad}

// ---------------------------------------------------------------------------
// K12: fused min/max + LUT build on disjoint block ranges (128-thr blocks so
// LUT MUFU work spreads ~1 warp/SMSP across the chip).
//   blocks [0,98):    chip-wide min/max of stressmap (atomics on g_stats.x/.y)
//   blocks [98,162):  LUT, 8 threads per entry (<=47-band MUFU chain each).
// ---------------------------------------------------------------------------
__global__ void __launch_bounds__(K12_TPB) k12_kernel(const float* __restrict__ sm,
                                                      const float* __restrict__ ss) {
    const int tid = threadIdx.x;

    if (blockIdx.x < MM_BLOCKS) {
        const int i = blockIdx.x * K12_TPB + tid;      // 0 .. 12543
        float4 v = ((const float4*)sm)[i];
        float mn = fminf(fminf(v.x, v.y), fminf(v.z, v.w));
        float mx = fmaxf(fmaxf(v.x, v.y), fmaxf(v.z, v.w));
        #pragma unroll
        for (int o = 16; o; o >>= 1) {
            mn = fminf(mn, __shfl_xor_sync(0xFFFFFFFFu, mn, o));
            mx = fmaxf(mx, __shfl_xor_sync(0xFFFFFFFFu, mx, o));
        }
        if ((tid & 31) == 0) {
            atomicMin(&g_stats.x, __float_as_uint(mn));
            atomicMax(&g_stats.y, __float_as_uint(mx));
        }
    } else {
        __shared__ float4 tab[S_BANDS];        // {1/lambda, w0, w1, w2}
        __shared__ float  s_a[3][K12_TPB];     // per-thread partials

        for (int s = tid; s < S_BANDS; s += K12_TPB) {
            tab[s] = make_float4(1.0f / (390.0f + (float)s),
                                 ss[3 * s + 0], ss[3 * s + 1], ss[3 * s + 2]);
        }
        __syncthreads();

        const int e = tid & (ENT_PER_BLK - 1);          // entry within block
        const int q = tid >> 4;                         // band octant 0..7
        const int i = (blockIdx.x - MM_BLOCKS) * ENT_PER_BLK + e;   // LUT index
        const float t = (float)i * (PHASE_SCALE / (float)(LUT_N - 1));

        const int s0 = q * 47;
        const int s1 = (q == 7) ? S_BANDS : s0 + 47;    // last octant: 42 bands

        // partial of sum_s w_sc*(1 - cos(t/lam_s)) over this octant
        float a0 = 0.f, a1 = 0.f, a2 = 0.f;
        for (int s = s0; s < s1; s++) {
            float4 v = tab[s];
            float c = 1.0f - __cosf(t * v.x);
            a0 = fmaf(v.y, c, a0);
            a1 = fmaf(v.z, c, a1);
            a2 = fmaf(v.w, c, a2);
        }
        s_a[0][tid] = a0; s_a[1][tid] = a1; s_a[2][tid] = a2;
        __syncthreads();

        if (q == 0) {   // threads 0..15 finalize the block's 16 entries
            float F[3];
            #pragma unroll
            for (int c = 0; c < 3; c++) {
                float acc = s_a[c][e];
                #pragma unroll
                for (int w = 1; w < 8; w++) acc += s_a[c][e + ENT_PER_BLK * w];
                F[c] = 0.5f * acc;
            }
            g_lut[i] = make_float4(F[0], F[1], F[2], 0.f);

            float m = fmaxf(F[0], fmaxf(F[1], F[2]));
            #pragma unroll
            for (int o = 8; o; o >>= 1) m = fmaxf(m, __shfl_xor_sync(0xFFFFu, m, o));
            if (e == 0) atomicMax(&g_stats.z, __float_as_uint(m));
        }
    }
}

// ---------------------------------------------------------------------------
// K3: per-pixel lerp + normalize + store, x2 (float2), PDL-launched.
// Input load issued BEFORE cudaGridDependencySynchronize(); stats fetched by
// every thread (one L1-broadcast LDG.128, no smem roundtrip). Final barrier
// before the ticket: output stores data-depend on the stats values, so every
// thread's stats read is consumed before the barrier -> reads precede reset.
// ---------------------------------------------------------------------------
__global__ void __launch_bounds__(256) pixel_kernel(const float* __restrict__ sm,
                                                    float* __restrict__ out) {
    const int tid = threadIdx.x;
    const int p2  = blockIdx.x * 256 + tid;          // 0 .. 25087

    const float2 x = ((const float2*)sm)[p2];        // independent of K12

    cudaGridDependencySynchronize();                 // K12's writes now visible

    unsigned sx, sy, sz, swu;
    asm volatile("ld.global.v4.u32 {%0,%1,%2,%3}, [%4];"
                 : "=r"(sx), "=r"(sy), "=r"(sz), "=r"(swu)
                 : "l"(&g_stats) : "memory");        // one LDG.128, L1-bcast
    (void)swu;
    const float mn     = __uint_as_float(sx);
    const float invrng = (float)(LUT_N - 1) / (__uint_as_float(sy) - mn);
    const float inv    = 1.0f / __uint_as_float(sz);

    float r0[2], r1[2], r2[2];
    const float xs[2] = {x.x, x.y};
    #pragma unroll
    for (int k = 0; k < 2; k++) {
        float u = (xs[k] - mn) * invrng;             // 0 .. LUT_N-1
        int   i = (int)u;
        i = (i < 0) ? 0 : ((i > LUT_N - 2) ? LUT_N - 2 : i);
        float fr = u - (float)i;
        float4 a = g_lut[i];
        float4 b = g_lut[i + 1];
        r0[k] = fmaf(fr, b.x - a.x, a.x) * inv;
        r1[k] = fmaf(fr, b.y - a.y, a.y) * inv;
        r2[k] = fmaf(fr, b.z - a.z, a.z) * inv;
    }

    float2* o2 = (float2*)out;
    o2[p2]          = make_float2(r0[0], r0[1]);
    o2[HW / 2 + p2] = make_float2(r1[0], r1[1]);
    o2[HW + p2]     = make_float2(r2[0], r2[1]);

    __syncthreads();   // all threads' stats reads are consumed by now

    // last-one-out reset: every block's reads precede its ticket.
    if (tid == 0) {
        __threadfence();
        unsigned t = atomicAdd(&g_stats.w, 1u);
        if (t == gridDim.x - 1) {
            g_stats.x = MIN_INIT;
            g_stats.y = 0u;
            g_stats.z = 0u;
            g_stats.w = 0u;
            __threadfence();
        }
    }
}

extern "C" void kernel_launch(void* const* d_in, const int* in_sizes, int n_in,
                              void* d_out, int out_size) {
    const float* sm = (const float*)d_in[0];
    const float* ss = (const float*)d_in[1];
    if (in_sizes[0] != HW) {   // defensive: identify by element count
        sm = (const float*)d_in[1];
        ss = (const float*)d_in[0];
    }
    float* out = (float*)d_out;

    k12_kernel<<<K12_BLOCKS, K12_TPB>>>(sm, ss);     // 162 blocks x 128 thr

    // PDL: pixel kernel launches early; orders itself via griddepsync.
    cudaLaunchConfig_t cfg = {};
    cfg.gridDim  = dim3(HW / 2 / 256);               // 98 blocks
    cfg.blockDim = dim3(256);
    cudaLaunchAttribute attr[1];
    attr[0].id = cudaLaunchAttributeProgrammaticStreamSerialization;
    attr[0].val.programmaticStreamSerializationAllowed = 1;
    cfg.attrs = attr;
    cfg.numAttrs = 1;
    cudaLaunchKernelEx(&cfg, pixel_kernel, sm, out);
}